// round 13
// baseline (speedup 1.0000x reference)
#include <cuda_runtime.h>
#include <cuda_bf16.h>
#include <cstdint>

#define CC 64
#define HH 128
#define WW 128
#define NN 4096
#define NS 8
#define BB 2

__device__ float g_a[NS][CC][NN];
__device__ float g_b[NS][CC][NN];
__device__ float g_Z[NS][NN];
__device__ float g_rZ[NS][NN];
__device__ float g_o[NS][CC][NN];
__device__ __nv_bfloat16 g_qh[NS][NN][CC], g_ql[NS][NN][CC];
__device__ __nv_bfloat16 g_kh[NS][NN][CC], g_kl[NS][NN][CC];
__device__ __nv_bfloat16 g_as[NS][2 * CC][NN], g_bs[NS][2 * CC][NN];
__device__ __nv_bfloat16 g_Eh[(size_t)NS * NN * NN], g_El[(size_t)NS * NN * NN];

__device__ __forceinline__ uint32_t s2u(const void* p) {
    uint32_t a;
    asm("{ .reg .u64 t; cvta.to.shared.u64 t, %1; cvt.u32.u64 %0, t; }" : "=r"(a) : "l"(p));
    return a;
}
__device__ __forceinline__ void ldsm4(uint32_t* r, uint32_t a) {
    asm volatile("ldmatrix.sync.aligned.m8n8.x4.shared.b16 {%0,%1,%2,%3}, [%4];"
        : "=r"(r[0]), "=r"(r[1]), "=r"(r[2]), "=r"(r[3]) : "r"(a));
}
__device__ __forceinline__ void ldsm4t(uint32_t* r, uint32_t a) {
    asm volatile("ldmatrix.sync.aligned.m8n8.x4.trans.shared.b16 {%0,%1,%2,%3}, [%4];"
        : "=r"(r[0]), "=r"(r[1]), "=r"(r[2]), "=r"(r[3]) : "r"(a));
}
__device__ __forceinline__ void mma16816(float* d, const uint32_t* a, const uint32_t* b) {
    asm volatile("mma.sync.aligned.m16n8k16.row.col.f32.bf16.bf16.f32 "
        "{%0,%1,%2,%3}, {%4,%5,%6,%7}, {%8,%9}, {%0,%1,%2,%3};"
        : "+f"(d[0]), "+f"(d[1]), "+f"(d[2]), "+f"(d[3])
        : "r"(a[0]), "r"(a[1]), "r"(a[2]), "r"(a[3]), "r"(b[0]), "r"(b[1]));
}
__device__ __forceinline__ uint32_t pk(float a, float b) {
    __nv_bfloat162 t(__float2bfloat16(a), __float2bfloat16(b));
    return *reinterpret_cast<uint32_t*>(&t);
}

// exp(s/8) on the FMA pipe (no MUFU): 2^y, y = s*0.125*log2e
__device__ __forceinline__ float fexp8(float s) {
    const float MAGIC = 12582912.0f;  // 1.5 * 2^23
    float y = s * 0.18033688011112042f;
    float t = y + MAGIC;
    float f = y - (t - MAGIC);        // f in [-0.5, 0.5]
    float p = 1.60218936e-3f;
    p = fmaf(p, f, 9.61739095e-3f);
    p = fmaf(p, f, 5.55041086e-2f);
    p = fmaf(p, f, 2.40226507e-1f);
    p = fmaf(p, f, 6.93147182e-1f);
    p = fmaf(p, f, 1.0f);
    return __int_as_float(__float_as_int(p) + (__float_as_int(t) << 23));
}

__global__ void zeroZ_kernel() {
    int i = blockIdx.x * 256 + threadIdx.x;
    if (i < NS * NN) (&g_Z[0][0])[i] = 0.0f;
}

// -------- conv: q,k -> split bf16 [n][c]; a,b -> fp32 [c][n] --------
__global__ void conv4_kernel(const float* __restrict__ x,
                             const float* __restrict__ Wq, const float* __restrict__ bq,
                             const float* __restrict__ Wk, const float* __restrict__ bk,
                             const float* __restrict__ Wa, const float* __restrict__ ba,
                             const float* __restrict__ Wb, const float* __restrict__ bb) {
    __shared__ float xs[CC][64];
    int wt = blockIdx.x, h = blockIdx.y, b = blockIdx.z, tid = threadIdx.x;
    for (int i = tid; i < CC * 64; i += 256)
        xs[i >> 6][i & 63] = x[(((size_t)b * CC + (i >> 6)) * HH + h) * WW + wt * 64 + (i & 63)];
    __syncthreads();
    int p = tid & 63, grp = tid >> 6;
    int s = b * 4 + (h >> 6) * 2 + wt;
    int n = (h & 63) * 64 + p;
    const float* Wm = (grp == 0) ? Wq : (grp == 1) ? Wk : (grp == 2) ? Wa : Wb;
    const float* bv = (grp == 0) ? bq : (grp == 1) ? bk : (grp == 2) ? ba : bb;
    if (grp < 2) {
        float av[CC];
        #pragma unroll 1
        for (int oc = 0; oc < CC; oc++) {
            float acc = bv[oc];
            const float4* wr = (const float4*)(Wm + oc * CC);
            #pragma unroll
            for (int c4 = 0; c4 < 16; c4++) {
                float4 w = wr[c4];
                acc += w.x * xs[c4 * 4][p] + w.y * xs[c4 * 4 + 1][p] + w.z * xs[c4 * 4 + 2][p] + w.w * xs[c4 * 4 + 3][p];
            }
            av[oc] = acc;
        }
        uint32_t* ph = (uint32_t*)((grp == 0) ? &g_qh[s][n][0] : &g_kh[s][n][0]);
        uint32_t* pl = (uint32_t*)((grp == 0) ? &g_ql[s][n][0] : &g_kl[s][n][0]);
        #pragma unroll
        for (int c2 = 0; c2 < 32; c2++) {
            float v0 = av[2 * c2], v1 = av[2 * c2 + 1];
            float h0 = __bfloat162float(__float2bfloat16(v0));
            float h1 = __bfloat162float(__float2bfloat16(v1));
            ph[c2] = pk(v0, v1);
            pl[c2] = pk(v0 - h0, v1 - h1);
        }
    } else {
        float* outp = (grp == 2) ? &g_a[s][0][0] : &g_b[s][0][0];
        #pragma unroll 1
        for (int oc = 0; oc < CC; oc++) {
            float acc = bv[oc];
            const float4* wr = (const float4*)(Wm + oc * CC);
            #pragma unroll
            for (int c4 = 0; c4 < 16; c4++) {
                float4 w = wr[c4];
                acc += w.x * xs[c4 * 4][p] + w.y * xs[c4 * 4 + 1][p] + w.z * xs[c4 * 4 + 2][p] + w.w * xs[c4 * 4 + 3][p];
            }
            outp[oc * NN + n] = acc;
        }
    }
}

// -------- ez: E = exp(q^T k / 8) via mma.sync, split store, Z rowsums --------
__global__ void __launch_bounds__(256, 2) ez_kernel() {
    extern __shared__ char sm[];
    uint32_t sb = s2u(sm);
    int s = blockIdx.z, n0 = blockIdx.y * 128, m0 = blockIdx.x * 128;
    int tid = threadIdx.x, w = tid >> 5, ln = tid & 31;
    const __nv_bfloat16* srcs[4] = {&g_qh[s][n0][0], &g_ql[s][n0][0], &g_kh[s][m0][0], &g_kl[s][m0][0]};
    #pragma unroll
    for (int pl = 0; pl < 4; pl++) {
        const uint4* sp = (const uint4*)srcs[pl];
        char* dp = sm + pl * 18432;
        for (int u = tid; u < 1024; u += 256)
            *(uint4*)(dp + (u >> 3) * 144 + (u & 7) * 16) = sp[u];
    }
    __syncthreads();
    int n_off = (w >> 1) * 32, m_off = (w & 1) * 64;
    int g = ln >> 2, tg = ln & 3;
    float acc[2][8][4];
    #pragma unroll
    for (int i = 0; i < 2; i++)
        #pragma unroll
        for (int j = 0; j < 8; j++)
            #pragma unroll
            for (int q = 0; q < 4; q++) acc[i][j][q] = 0.f;
    #pragma unroll 1
    for (int pass = 0; pass < 3; pass++) {
        uint32_t qb = sb + ((pass == 2) ? 18432u : 0u);
        uint32_t kb = sb + 36864u + ((pass == 1) ? 18432u : 0u);
        #pragma unroll
        for (int k16 = 0; k16 < 4; k16++) {
            int cb = k16 * 16;
            uint32_t aF[2][4];
            #pragma unroll
            for (int mf = 0; mf < 2; mf++)
                ldsm4(aF[mf], qb + (n_off + mf * 16 + (ln & 15)) * 144 + (cb + (ln >> 4) * 8) * 2);
            #pragma unroll
            for (int np = 0; np < 4; np++) {
                uint32_t bF[4];
                ldsm4(bF, kb + (m_off + np * 16 + (ln & 7) + ((ln >> 4) << 3)) * 144 + (cb + ((ln >> 3) & 1) * 8) * 2);
                mma16816(acc[0][2 * np], aF[0], bF);
                mma16816(acc[0][2 * np + 1], aF[0], bF + 2);
                mma16816(acc[1][2 * np], aF[1], bF);
                mma16816(acc[1][2 * np + 1], aF[1], bF + 2);
            }
        }
    }
    // exp (FMA-pipe) + row sums
    #pragma unroll
    for (int mf = 0; mf < 2; mf++) {
        float r0 = 0.f, r1 = 0.f;
        #pragma unroll
        for (int nf = 0; nf < 8; nf++) {
            #pragma unroll
            for (int q = 0; q < 4; q++) acc[mf][nf][q] = fexp8(acc[mf][nf][q]);
            r0 += acc[mf][nf][0] + acc[mf][nf][1];
            r1 += acc[mf][nf][2] + acc[mf][nf][3];
        }
        r0 += __shfl_xor_sync(~0u, r0, 1); r0 += __shfl_xor_sync(~0u, r0, 2);
        r1 += __shfl_xor_sync(~0u, r1, 1); r1 += __shfl_xor_sync(~0u, r1, 2);
        if (tg == 0) {
            atomicAdd(&g_Z[s][n0 + n_off + mf * 16 + g], r0);
            atomicAdd(&g_Z[s][n0 + n_off + mf * 16 + g + 8], r1);
        }
    }
    __syncthreads();
    #pragma unroll
    for (int mf = 0; mf < 2; mf++)
        #pragma unroll
        for (int nf = 0; nf < 8; nf++) {
            int col = m_off + nf * 8 + 2 * tg;
            int r0w = n_off + mf * 16 + g, r1w = r0w + 8;
            float v0 = acc[mf][nf][0], v1 = acc[mf][nf][1], v2 = acc[mf][nf][2], v3 = acc[mf][nf][3];
            float h0 = __bfloat162float(__float2bfloat16(v0));
            float h1 = __bfloat162float(__float2bfloat16(v1));
            float h2 = __bfloat162float(__float2bfloat16(v2));
            float h3 = __bfloat162float(__float2bfloat16(v3));
            *(uint32_t*)(sm + r0w * 272 + col * 2) = pk(v0, v1);
            *(uint32_t*)(sm + 36864 + r0w * 272 + col * 2) = pk(v0 - h0, v1 - h1);
            *(uint32_t*)(sm + r1w * 272 + col * 2) = pk(v2, v3);
            *(uint32_t*)(sm + 36864 + r1w * 272 + col * 2) = pk(v2 - h2, v3 - h3);
        }
    __syncthreads();
    for (int u = tid; u < 2048; u += 256) {
        int row = u >> 4, ch = u & 15;
        size_t base = ((size_t)s * NN + n0 + row) * NN + m0 + ch * 8;
        *(uint4*)&g_Eh[base] = *(uint4*)(sm + row * 272 + ch * 16);
        *(uint4*)&g_El[base] = *(uint4*)(sm + 36864 + row * 272 + ch * 16);
    }
}

// -------- scale a by 1/Z, split a,b into stacked hi/lo bf16 --------
__global__ void scale_split_kernel() {
    int n = blockIdx.x * 256 + threadIdx.x, c = blockIdx.y, s = blockIdx.z;
    float rz = 1.0f / g_Z[s][n];
    if (c == 0) g_rZ[s][n] = rz;
    float av = g_a[s][c][n] * rz, bv = g_b[s][c][n];
    float ah = __bfloat162float(__float2bfloat16(av));
    float bh = __bfloat162float(__float2bfloat16(bv));
    g_as[s][c][n] = __float2bfloat16(av);
    g_as[s][c + CC][n] = __float2bfloat16(av - ah);
    g_bs[s][c][n] = __float2bfloat16(bv);
    g_bs[s][c + CC][n] = __float2bfloat16(bv - bh);
}

// -------- outk: out = a'@E + diag(rZ)*(b @ E-rows) via mma.sync --------
__global__ void __launch_bounds__(256, 2) outk_kernel() {
    extern __shared__ char sm[];
    uint32_t sb = s2u(sm);
    int s = blockIdx.y, m0 = blockIdx.x * 128;
    int tid = threadIdx.x, w = tid >> 5, ln = tid & 31;
    const uint32_t AH = 0, AL = 9216, BH = 18432, BL = 27648;
    const uint32_t E1H = 36864, E1L = 54272, E2H = 71680, E2L = 90112;
    int c_off = (w >> 1) * 16, mw = (w & 1) * 64;
    int g = ln >> 2, tg = ln & 3;
    float ac1[8][4], ac2[8][4];
    #pragma unroll
    for (int i = 0; i < 8; i++)
        #pragma unroll
        for (int q = 0; q < 4; q++) { ac1[i][q] = 0.f; ac2[i][q] = 0.f; }

    #pragma unroll 1
    for (int it = 0; it < 64; it++) {
        int j0 = it * 64;
        __syncthreads();
        for (int u = tid; u < 2048; u += 256) {
            int pl = u >> 9, rem = u & 511, row = rem >> 3, ch = rem & 7;
            const __nv_bfloat16* src = (pl < 2) ? &g_as[s][row + (pl & 1) * 64][j0]
                                                : &g_bs[s][row + (pl & 1) * 64][j0];
            *(uint4*)(sm + pl * 9216 + row * 144 + ch * 16) = ((const uint4*)src)[ch];
        }
        for (int u = tid; u < 2048; u += 256) {
            int pl = u >> 10, rem = u & 1023, row = rem >> 4, ch = rem & 15;
            const __nv_bfloat16* src = pl ? &g_El[((size_t)s * NN + j0 + row) * NN + m0]
                                          : &g_Eh[((size_t)s * NN + j0 + row) * NN + m0];
            *(uint4*)(sm + E1H + pl * 17408 + row * 272 + ch * 16) = ((const uint4*)src)[ch];
        }
        for (int u = tid; u < 2048; u += 256) {
            int pl = u >> 10, rem = u & 1023, row = rem >> 3, ch = rem & 7;
            const __nv_bfloat16* src = pl ? &g_El[((size_t)s * NN + m0 + row) * NN + j0]
                                          : &g_Eh[((size_t)s * NN + m0 + row) * NN + j0];
            *(uint4*)(sm + E2H + pl * 18432 + row * 144 + ch * 16) = ((const uint4*)src)[ch];
        }
        __syncthreads();
        #pragma unroll
        for (int kb = 0; kb < 4; kb++) {
            int jb = kb * 16;
            uint32_t ah[4], al[4], bh[4], bl[4];
            uint32_t arow = (c_off + (ln & 15)) * 144 + (jb + (ln >> 4) * 8) * 2;
            ldsm4(ah, sb + AH + arow);
            ldsm4(al, sb + AL + arow);
            ldsm4(bh, sb + BH + arow);
            ldsm4(bl, sb + BL + arow);
            #pragma unroll
            for (int np = 0; np < 4; np++) {
                int mb = mw + np * 16;
                uint32_t e1h[4], e1l[4], e2h[4], e2l[4];
                uint32_t t1a = (jb + (ln & 15)) * 272 + (mb + (ln >> 4) * 8) * 2;
                ldsm4t(e1h, sb + E1H + t1a);
                ldsm4t(e1l, sb + E1L + t1a);
                uint32_t t2a = (mb + (ln & 7) + ((ln >> 4) << 3)) * 144 + (jb + ((ln >> 3) & 1) * 8) * 2;
                ldsm4(e2h, sb + E2H + t2a);
                ldsm4(e2l, sb + E2L + t2a);
                mma16816(ac1[2 * np], ah, e1h);     mma16816(ac1[2 * np + 1], ah, e1h + 2);
                mma16816(ac1[2 * np], al, e1h);     mma16816(ac1[2 * np + 1], al, e1h + 2);
                mma16816(ac1[2 * np], ah, e1l);     mma16816(ac1[2 * np + 1], ah, e1l + 2);
                mma16816(ac2[2 * np], bh, e2h);     mma16816(ac2[2 * np + 1], bh, e2h + 2);
                mma16816(ac2[2 * np], bl, e2h);     mma16816(ac2[2 * np + 1], bl, e2h + 2);
                mma16816(ac2[2 * np], bh, e2l);     mma16816(ac2[2 * np + 1], bh, e2l + 2);
            }
        }
    }
    #pragma unroll
    for (int nf = 0; nf < 8; nf++) {
        int m = m0 + mw + nf * 8 + 2 * tg;
        float rz0 = g_rZ[s][m], rz1 = g_rZ[s][m + 1];
        int c0 = c_off + g;
        g_o[s][c0][m]     = ac1[nf][0] + rz0 * ac2[nf][0];
        g_o[s][c0][m + 1] = ac1[nf][1] + rz1 * ac2[nf][1];
        g_o[s][c0 + 8][m]     = ac1[nf][2] + rz0 * ac2[nf][2];
        g_o[s][c0 + 8][m + 1] = ac1[nf][3] + rz1 * ac2[nf][3];
    }
}

// -------- final 1x1 conv + un-regionize --------
__global__ void finalconv_kernel(const float* __restrict__ Wo, const float* __restrict__ bo,
                                 float* __restrict__ out) {
    __shared__ float os[CC][64];
    int wt = blockIdx.x, h = blockIdx.y, b = blockIdx.z, tid = threadIdx.x;
    int s = b * 4 + (h >> 6) * 2 + wt;
    int nb = (h & 63) * 64;
    for (int i = tid; i < CC * 64; i += 256)
        os[i >> 6][i & 63] = g_o[s][i >> 6][nb + (i & 63)];
    __syncthreads();
    int p = tid & 63, grp = tid >> 6;
    #pragma unroll 1
    for (int i = 0; i < 16; i++) {
        int oc = grp * 16 + i;
        float acc = bo[oc];
        const float4* wr = (const float4*)(Wo + oc * CC);
        #pragma unroll
        for (int c4 = 0; c4 < 16; c4++) {
            float4 w = wr[c4];
            acc += w.x * os[c4 * 4][p] + w.y * os[c4 * 4 + 1][p] + w.z * os[c4 * 4 + 2][p] + w.w * os[c4 * 4 + 3][p];
        }
        out[(((size_t)b * CC + oc) * HH + h) * WW + wt * 64 + p] = acc;
    }
}

extern "C" void kernel_launch(void* const* d_in, const int* in_sizes, int n_in,
                              void* d_out, int out_size) {
    const float* x = (const float*)d_in[0];
    const float *Wq = (const float*)d_in[1], *bq = (const float*)d_in[2];
    const float *Wk = (const float*)d_in[3], *bk = (const float*)d_in[4];
    const float *Wa = (const float*)d_in[5], *ba = (const float*)d_in[6];
    const float *Wb = (const float*)d_in[7], *bb = (const float*)d_in[8];
    const float *Wo = (const float*)d_in[9], *bo = (const float*)d_in[10];
    float* out = (float*)d_out;

    const int EZ_SM = 73728;
    const int OK_SM = 108544;
    cudaFuncSetAttribute(ez_kernel, cudaFuncAttributeMaxDynamicSharedMemorySize, EZ_SM);
    cudaFuncSetAttribute(outk_kernel, cudaFuncAttributeMaxDynamicSharedMemorySize, OK_SM);

    zeroZ_kernel<<<(NS * NN + 255) / 256, 256>>>();
    conv4_kernel<<<dim3(2, HH, BB), 256>>>(x, Wq, bq, Wk, bk, Wa, ba, Wb, bb);
    ez_kernel<<<dim3(32, 32, NS), 256, EZ_SM>>>();
    scale_split_kernel<<<dim3(NN / 256, CC, NS), 256>>>();
    outk_kernel<<<dim3(32, NS), 256, OK_SM>>>();
    finalconv_kernel<<<dim3(2, HH, BB), 256>>>(Wo, bo, out);
}

// round 14
// speedup vs baseline: 1.0087x; 1.0087x over previous
#include <cuda_runtime.h>
#include <cuda_bf16.h>
#include <cstdint>

#define CC 64
#define HH 128
#define WW 128
#define NN 4096
#define NS 8
#define BB 2

__device__ float g_a[NS][CC][NN];
__device__ float g_b[NS][CC][NN];
__device__ float g_Z[NS][NN];
__device__ float g_rZ[NS][NN];
__device__ float g_o[NS][CC][NN];
__device__ __nv_bfloat16 g_qh[NS][NN][CC], g_ql[NS][NN][CC];
__device__ __nv_bfloat16 g_kh[NS][NN][CC], g_kl[NS][NN][CC];
__device__ __nv_bfloat16 g_as[NS][2 * CC][NN], g_bs[NS][2 * CC][NN];
__device__ __nv_bfloat16 g_Eh[(size_t)NS * NN * NN];

__device__ __forceinline__ uint32_t s2u(const void* p) {
    uint32_t a;
    asm("{ .reg .u64 t; cvta.to.shared.u64 t, %1; cvt.u32.u64 %0, t; }" : "=r"(a) : "l"(p));
    return a;
}
__device__ __forceinline__ void ldsm4(uint32_t* r, uint32_t a) {
    asm volatile("ldmatrix.sync.aligned.m8n8.x4.shared.b16 {%0,%1,%2,%3}, [%4];"
        : "=r"(r[0]), "=r"(r[1]), "=r"(r[2]), "=r"(r[3]) : "r"(a));
}
__device__ __forceinline__ void ldsm4t(uint32_t* r, uint32_t a) {
    asm volatile("ldmatrix.sync.aligned.m8n8.x4.trans.shared.b16 {%0,%1,%2,%3}, [%4];"
        : "=r"(r[0]), "=r"(r[1]), "=r"(r[2]), "=r"(r[3]) : "r"(a));
}
__device__ __forceinline__ void mma16816(float* d, const uint32_t* a, const uint32_t* b) {
    asm volatile("mma.sync.aligned.m16n8k16.row.col.f32.bf16.bf16.f32 "
        "{%0,%1,%2,%3}, {%4,%5,%6,%7}, {%8,%9}, {%0,%1,%2,%3};"
        : "+f"(d[0]), "+f"(d[1]), "+f"(d[2]), "+f"(d[3])
        : "r"(a[0]), "r"(a[1]), "r"(a[2]), "r"(a[3]), "r"(b[0]), "r"(b[1]));
}
__device__ __forceinline__ uint32_t pk(float a, float b) {
    __nv_bfloat162 t(__float2bfloat16(a), __float2bfloat16(b));
    return *reinterpret_cast<uint32_t*>(&t);
}

// exp(s/8) on the FMA pipe
__device__ __forceinline__ float fexp8(float s) {
    const float MAGIC = 12582912.0f;  // 1.5 * 2^23
    float y = s * 0.18033688011112042f;
    float t = y + MAGIC;
    float f = y - (t - MAGIC);
    float p = 1.60218936e-3f;
    p = fmaf(p, f, 9.61739095e-3f);
    p = fmaf(p, f, 5.55041086e-2f);
    p = fmaf(p, f, 2.40226507e-1f);
    p = fmaf(p, f, 6.93147182e-1f);
    p = fmaf(p, f, 1.0f);
    return __int_as_float(__float_as_int(p) + (__float_as_int(t) << 23));
}

__global__ void zeroZ_kernel() {
    int i = blockIdx.x * 256 + threadIdx.x;
    if (i < NS * NN) (&g_Z[0][0])[i] = 0.0f;
}

// -------- conv: q,k -> split bf16 [n][c]; a,b -> fp32 [c][n] --------
__global__ void conv4_kernel(const float* __restrict__ x,
                             const float* __restrict__ Wq, const float* __restrict__ bq,
                             const float* __restrict__ Wk, const float* __restrict__ bk,
                             const float* __restrict__ Wa, const float* __restrict__ ba,
                             const float* __restrict__ Wb, const float* __restrict__ bb) {
    __shared__ float xs[CC][64];
    int wt = blockIdx.x, h = blockIdx.y, b = blockIdx.z, tid = threadIdx.x;
    for (int i = tid; i < CC * 64; i += 256)
        xs[i >> 6][i & 63] = x[(((size_t)b * CC + (i >> 6)) * HH + h) * WW + wt * 64 + (i & 63)];
    __syncthreads();
    int p = tid & 63, grp = tid >> 6;
    int s = b * 4 + (h >> 6) * 2 + wt;
    int n = (h & 63) * 64 + p;
    const float* Wm = (grp == 0) ? Wq : (grp == 1) ? Wk : (grp == 2) ? Wa : Wb;
    const float* bv = (grp == 0) ? bq : (grp == 1) ? bk : (grp == 2) ? ba : bb;
    if (grp < 2) {
        float av[CC];
        #pragma unroll 1
        for (int oc = 0; oc < CC; oc++) {
            float acc = bv[oc];
            const float4* wr = (const float4*)(Wm + oc * CC);
            #pragma unroll
            for (int c4 = 0; c4 < 16; c4++) {
                float4 w = wr[c4];
                acc += w.x * xs[c4 * 4][p] + w.y * xs[c4 * 4 + 1][p] + w.z * xs[c4 * 4 + 2][p] + w.w * xs[c4 * 4 + 3][p];
            }
            av[oc] = acc;
        }
        uint32_t* ph = (uint32_t*)((grp == 0) ? &g_qh[s][n][0] : &g_kh[s][n][0]);
        uint32_t* pl = (uint32_t*)((grp == 0) ? &g_ql[s][n][0] : &g_kl[s][n][0]);
        #pragma unroll
        for (int c2 = 0; c2 < 32; c2++) {
            float v0 = av[2 * c2], v1 = av[2 * c2 + 1];
            float h0 = __bfloat162float(__float2bfloat16(v0));
            float h1 = __bfloat162float(__float2bfloat16(v1));
            ph[c2] = pk(v0, v1);
            pl[c2] = pk(v0 - h0, v1 - h1);
        }
    } else {
        float* outp = (grp == 2) ? &g_a[s][0][0] : &g_b[s][0][0];
        #pragma unroll 1
        for (int oc = 0; oc < CC; oc++) {
            float acc = bv[oc];
            const float4* wr = (const float4*)(Wm + oc * CC);
            #pragma unroll
            for (int c4 = 0; c4 < 16; c4++) {
                float4 w = wr[c4];
                acc += w.x * xs[c4 * 4][p] + w.y * xs[c4 * 4 + 1][p] + w.z * xs[c4 * 4 + 2][p] + w.w * xs[c4 * 4 + 3][p];
            }
            outp[oc * NN + n] = acc;
        }
    }
}

// -------- ez: E = exp(q^T k / 8) via mma.sync, bf16 store, Z rowsums --------
__global__ void __launch_bounds__(256, 2) ez_kernel() {
    extern __shared__ char sm[];
    uint32_t sb = s2u(sm);
    int s = blockIdx.z, n0 = blockIdx.y * 128, m0 = blockIdx.x * 128;
    int tid = threadIdx.x, w = tid >> 5, ln = tid & 31;
    const __nv_bfloat16* srcs[4] = {&g_qh[s][n0][0], &g_ql[s][n0][0], &g_kh[s][m0][0], &g_kl[s][m0][0]};
    #pragma unroll
    for (int pl = 0; pl < 4; pl++) {
        const uint4* sp = (const uint4*)srcs[pl];
        char* dp = sm + pl * 18432;
        for (int u = tid; u < 1024; u += 256)
            *(uint4*)(dp + (u >> 3) * 144 + (u & 7) * 16) = sp[u];
    }
    __syncthreads();
    int n_off = (w >> 1) * 32, m_off = (w & 1) * 64;
    int g = ln >> 2, tg = ln & 3;
    float acc[2][8][4];
    #pragma unroll
    for (int i = 0; i < 2; i++)
        #pragma unroll
        for (int j = 0; j < 8; j++)
            #pragma unroll
            for (int q = 0; q < 4; q++) acc[i][j][q] = 0.f;
    #pragma unroll 1
    for (int pass = 0; pass < 3; pass++) {
        uint32_t qb = sb + ((pass == 2) ? 18432u : 0u);
        uint32_t kb = sb + 36864u + ((pass == 1) ? 18432u : 0u);
        #pragma unroll
        for (int k16 = 0; k16 < 4; k16++) {
            int cb = k16 * 16;
            uint32_t aF[2][4];
            #pragma unroll
            for (int mf = 0; mf < 2; mf++)
                ldsm4(aF[mf], qb + (n_off + mf * 16 + (ln & 15)) * 144 + (cb + (ln >> 4) * 8) * 2);
            #pragma unroll
            for (int np = 0; np < 4; np++) {
                uint32_t bF[4];
                ldsm4(bF, kb + (m_off + np * 16 + (ln & 7) + ((ln >> 4) << 3)) * 144 + (cb + ((ln >> 3) & 1) * 8) * 2);
                mma16816(acc[0][2 * np], aF[0], bF);
                mma16816(acc[0][2 * np + 1], aF[0], bF + 2);
                mma16816(acc[1][2 * np], aF[1], bF);
                mma16816(acc[1][2 * np + 1], aF[1], bF + 2);
            }
        }
    }
    // exp + row sums
    #pragma unroll
    for (int mf = 0; mf < 2; mf++) {
        float r0 = 0.f, r1 = 0.f;
        #pragma unroll
        for (int nf = 0; nf < 8; nf++) {
            #pragma unroll
            for (int q = 0; q < 4; q++) acc[mf][nf][q] = fexp8(acc[mf][nf][q]);
            r0 += acc[mf][nf][0] + acc[mf][nf][1];
            r1 += acc[mf][nf][2] + acc[mf][nf][3];
        }
        r0 += __shfl_xor_sync(~0u, r0, 1); r0 += __shfl_xor_sync(~0u, r0, 2);
        r1 += __shfl_xor_sync(~0u, r1, 1); r1 += __shfl_xor_sync(~0u, r1, 2);
        if (tg == 0) {
            atomicAdd(&g_Z[s][n0 + n_off + mf * 16 + g], r0);
            atomicAdd(&g_Z[s][n0 + n_off + mf * 16 + g + 8], r1);
        }
    }
    __syncthreads();
    // stage hi plane [128][136] bf16 (272B rows) for coalesced store
    #pragma unroll
    for (int mf = 0; mf < 2; mf++)
        #pragma unroll
        for (int nf = 0; nf < 8; nf++) {
            int col = m_off + nf * 8 + 2 * tg;
            int r0w = n_off + mf * 16 + g, r1w = r0w + 8;
            *(uint32_t*)(sm + r0w * 272 + col * 2) = pk(acc[mf][nf][0], acc[mf][nf][1]);
            *(uint32_t*)(sm + r1w * 272 + col * 2) = pk(acc[mf][nf][2], acc[mf][nf][3]);
        }
    __syncthreads();
    for (int u = tid; u < 2048; u += 256) {
        int row = u >> 4, ch = u & 15;
        *(uint4*)&g_Eh[((size_t)s * NN + n0 + row) * NN + m0 + ch * 8] = *(uint4*)(sm + row * 272 + ch * 16);
    }
}

// -------- scale a by 1/Z, split a,b into stacked hi/lo bf16 --------
__global__ void scale_split_kernel() {
    int n = blockIdx.x * 256 + threadIdx.x, c = blockIdx.y, s = blockIdx.z;
    float rz = 1.0f / g_Z[s][n];
    if (c == 0) g_rZ[s][n] = rz;
    float av = g_a[s][c][n] * rz, bv = g_b[s][c][n];
    float ah = __bfloat162float(__float2bfloat16(av));
    float bh = __bfloat162float(__float2bfloat16(bv));
    g_as[s][c][n] = __float2bfloat16(av);
    g_as[s][c + CC][n] = __float2bfloat16(av - ah);
    g_bs[s][c][n] = __float2bfloat16(bv);
    g_bs[s][c + CC][n] = __float2bfloat16(bv - bh);
}

// -------- outk: out = a'@E + diag(rZ)*(b @ E-rows) via mma.sync --------
__global__ void __launch_bounds__(256, 2) outk_kernel() {
    extern __shared__ char sm[];
    uint32_t sb = s2u(sm);
    int s = blockIdx.y, m0 = blockIdx.x * 128;
    int tid = threadIdx.x, w = tid >> 5, ln = tid & 31;
    const uint32_t AH = 0, AL = 9216, BH = 18432, BL = 27648;
    const uint32_t E1H = 36864, E2H = 54272;   // E1: 64x272B=17408, E2: 128x144B=18432
    int c_off = (w >> 1) * 16, mw = (w & 1) * 64;
    int g = ln >> 2, tg = ln & 3;
    float ac1[8][4], ac2[8][4];
    #pragma unroll
    for (int i = 0; i < 8; i++)
        #pragma unroll
        for (int q = 0; q < 4; q++) { ac1[i][q] = 0.f; ac2[i][q] = 0.f; }

    #pragma unroll 1
    for (int it = 0; it < 64; it++) {
        int j0 = it * 64;
        __syncthreads();
        for (int u = tid; u < 2048; u += 256) {
            int pl = u >> 9, rem = u & 511, row = rem >> 3, ch = rem & 7;
            const __nv_bfloat16* src = (pl < 2) ? &g_as[s][row + (pl & 1) * 64][j0]
                                                : &g_bs[s][row + (pl & 1) * 64][j0];
            *(uint4*)(sm + pl * 9216 + row * 144 + ch * 16) = ((const uint4*)src)[ch];
        }
        // E1 [64j][128m] (term1, via ldmatrix.trans)
        for (int u = tid; u < 1024; u += 256) {
            int row = u >> 4, ch = u & 15;
            *(uint4*)(sm + E1H + row * 272 + ch * 16) =
                ((const uint4*)&g_Eh[((size_t)s * NN + j0 + row) * NN + m0])[ch];
        }
        // E2 [128m][64j] (term2, K-major direct)
        for (int u = tid; u < 1024; u += 256) {
            int row = u >> 3, ch = u & 7;
            *(uint4*)(sm + E2H + row * 144 + ch * 16) =
                ((const uint4*)&g_Eh[((size_t)s * NN + m0 + row) * NN + j0])[ch];
        }
        __syncthreads();
        #pragma unroll
        for (int kb = 0; kb < 4; kb++) {
            int jb = kb * 16;
            uint32_t ah[4], al[4], bh[4], bl[4];
            uint32_t arow = (c_off + (ln & 15)) * 144 + (jb + (ln >> 4) * 8) * 2;
            ldsm4(ah, sb + AH + arow);
            ldsm4(al, sb + AL + arow);
            ldsm4(bh, sb + BH + arow);
            ldsm4(bl, sb + BL + arow);
            #pragma unroll
            for (int np = 0; np < 4; np++) {
                int mb = mw + np * 16;
                uint32_t e1h[4], e2h[4];
                ldsm4t(e1h, sb + E1H + (jb + (ln & 15)) * 272 + (mb + (ln >> 4) * 8) * 2);
                ldsm4(e2h, sb + E2H + (mb + (ln & 7) + ((ln >> 4) << 3)) * 144 + (jb + ((ln >> 3) & 1) * 8) * 2);
                mma16816(ac1[2 * np], ah, e1h);     mma16816(ac1[2 * np + 1], ah, e1h + 2);
                mma16816(ac1[2 * np], al, e1h);     mma16816(ac1[2 * np + 1], al, e1h + 2);
                mma16816(ac2[2 * np], bh, e2h);     mma16816(ac2[2 * np + 1], bh, e2h + 2);
                mma16816(ac2[2 * np], bl, e2h);     mma16816(ac2[2 * np + 1], bl, e2h + 2);
            }
        }
    }
    #pragma unroll
    for (int nf = 0; nf < 8; nf++) {
        int m = m0 + mw + nf * 8 + 2 * tg;
        float rz0 = g_rZ[s][m], rz1 = g_rZ[s][m + 1];
        int c0 = c_off + g;
        g_o[s][c0][m]     = ac1[nf][0] + rz0 * ac2[nf][0];
        g_o[s][c0][m + 1] = ac1[nf][1] + rz1 * ac2[nf][1];
        g_o[s][c0 + 8][m]     = ac1[nf][2] + rz0 * ac2[nf][2];
        g_o[s][c0 + 8][m + 1] = ac1[nf][3] + rz1 * ac2[nf][3];
    }
}

// -------- final 1x1 conv + un-regionize --------
__global__ void finalconv_kernel(const float* __restrict__ Wo, const float* __restrict__ bo,
                                 float* __restrict__ out) {
    __shared__ float os[CC][64];
    int wt = blockIdx.x, h = blockIdx.y, b = blockIdx.z, tid = threadIdx.x;
    int s = b * 4 + (h >> 6) * 2 + wt;
    int nb = (h & 63) * 64;
    for (int i = tid; i < CC * 64; i += 256)
        os[i >> 6][i & 63] = g_o[s][i >> 6][nb + (i & 63)];
    __syncthreads();
    int p = tid & 63, grp = tid >> 6;
    #pragma unroll 1
    for (int i = 0; i < 16; i++) {
        int oc = grp * 16 + i;
        float acc = bo[oc];
        const float4* wr = (const float4*)(Wo + oc * CC);
        #pragma unroll
        for (int c4 = 0; c4 < 16; c4++) {
            float4 w = wr[c4];
            acc += w.x * os[c4 * 4][p] + w.y * os[c4 * 4 + 1][p] + w.z * os[c4 * 4 + 2][p] + w.w * os[c4 * 4 + 3][p];
        }
        out[(((size_t)b * CC + oc) * HH + h) * WW + wt * 64 + p] = acc;
    }
}

extern "C" void kernel_launch(void* const* d_in, const int* in_sizes, int n_in,
                              void* d_out, int out_size) {
    const float* x = (const float*)d_in[0];
    const float *Wq = (const float*)d_in[1], *bq = (const float*)d_in[2];
    const float *Wk = (const float*)d_in[3], *bk = (const float*)d_in[4];
    const float *Wa = (const float*)d_in[5], *ba = (const float*)d_in[6];
    const float *Wb = (const float*)d_in[7], *bb = (const float*)d_in[8];
    const float *Wo = (const float*)d_in[9], *bo = (const float*)d_in[10];
    float* out = (float*)d_out;

    const int EZ_SM = 73728;
    const int OK_SM = 72704;
    cudaFuncSetAttribute(ez_kernel, cudaFuncAttributeMaxDynamicSharedMemorySize, EZ_SM);
    cudaFuncSetAttribute(outk_kernel, cudaFuncAttributeMaxDynamicSharedMemorySize, OK_SM);

    zeroZ_kernel<<<(NS * NN + 255) / 256, 256>>>();
    conv4_kernel<<<dim3(2, HH, BB), 256>>>(x, Wq, bq, Wk, bk, Wa, ba, Wb, bb);
    ez_kernel<<<dim3(32, 32, NS), 256, EZ_SM>>>();
    scale_split_kernel<<<dim3(NN / 256, CC, NS), 256>>>();
    outk_kernel<<<dim3(32, NS), 256, OK_SM>>>();
    finalconv_kernel<<<dim3(2, HH, BB), 256>>>(Wo, bo, out);
}

// round 15
// speedup vs baseline: 1.0093x; 1.0006x over previous
#include <cuda_runtime.h>
#include <cuda_bf16.h>
#include <cstdint>

#define CC 64
#define HH 128
#define WW 128
#define NN 4096
#define NS 8
#define BB 2

__device__ float g_a[NS][CC][NN];
__device__ float g_b[NS][CC][NN];
__device__ float g_Z[NS][NN];
__device__ float g_rZ[NS][NN];
__device__ float g_o[NS][CC][NN];
__device__ __nv_bfloat16 g_qh[NS][NN][CC], g_ql[NS][NN][CC];
__device__ __nv_bfloat16 g_kh[NS][NN][CC], g_kl[NS][NN][CC];
__device__ __nv_bfloat16 g_as[NS][2 * CC][NN], g_bs[NS][2 * CC][NN];
__device__ __nv_bfloat16 g_Eh[(size_t)NS * NN * NN];

__device__ __forceinline__ uint32_t s2u(const void* p) {
    uint32_t a;
    asm("{ .reg .u64 t; cvta.to.shared.u64 t, %1; cvt.u32.u64 %0, t; }" : "=r"(a) : "l"(p));
    return a;
}
__device__ __forceinline__ void ldsm4(uint32_t* r, uint32_t a) {
    asm volatile("ldmatrix.sync.aligned.m8n8.x4.shared.b16 {%0,%1,%2,%3}, [%4];"
        : "=r"(r[0]), "=r"(r[1]), "=r"(r[2]), "=r"(r[3]) : "r"(a));
}
__device__ __forceinline__ void ldsm4t(uint32_t* r, uint32_t a) {
    asm volatile("ldmatrix.sync.aligned.m8n8.x4.trans.shared.b16 {%0,%1,%2,%3}, [%4];"
        : "=r"(r[0]), "=r"(r[1]), "=r"(r[2]), "=r"(r[3]) : "r"(a));
}
__device__ __forceinline__ void mma16816(float* d, const uint32_t* a, const uint32_t* b) {
    asm volatile("mma.sync.aligned.m16n8k16.row.col.f32.bf16.bf16.f32 "
        "{%0,%1,%2,%3}, {%4,%5,%6,%7}, {%8,%9}, {%0,%1,%2,%3};"
        : "+f"(d[0]), "+f"(d[1]), "+f"(d[2]), "+f"(d[3])
        : "r"(a[0]), "r"(a[1]), "r"(a[2]), "r"(a[3]), "r"(b[0]), "r"(b[1]));
}
__device__ __forceinline__ uint32_t pk(float a, float b) {
    __nv_bfloat162 t(__float2bfloat16(a), __float2bfloat16(b));
    return *reinterpret_cast<uint32_t*>(&t);
}

// exp(s/8) on the FMA pipe
__device__ __forceinline__ float fexp8(float s) {
    const float MAGIC = 12582912.0f;  // 1.5 * 2^23
    float y = s * 0.18033688011112042f;
    float t = y + MAGIC;
    float f = y - (t - MAGIC);
    float p = 1.60218936e-3f;
    p = fmaf(p, f, 9.61739095e-3f);
    p = fmaf(p, f, 5.55041086e-2f);
    p = fmaf(p, f, 2.40226507e-1f);
    p = fmaf(p, f, 6.93147182e-1f);
    p = fmaf(p, f, 1.0f);
    return __int_as_float(__float_as_int(p) + (__float_as_int(t) << 23));
}

// -------- conv (+ inline Z zeroing): q,k -> split bf16 [n][c]; a,b -> fp32 [c][n] --------
__global__ void conv4_kernel(const float* __restrict__ x,
                             const float* __restrict__ Wq, const float* __restrict__ bq,
                             const float* __restrict__ Wk, const float* __restrict__ bk,
                             const float* __restrict__ Wa, const float* __restrict__ ba,
                             const float* __restrict__ Wb, const float* __restrict__ bb) {
    __shared__ float xs[CC][64];
    int wt = blockIdx.x, h = blockIdx.y, b = blockIdx.z, tid = threadIdx.x;
    // zero g_Z (replaces zeroZ_kernel; safe — ez runs after this kernel completes)
    {
        int gi = (((b * HH) + h) * 2 + wt) * 256 + tid;
        if (gi < NS * NN) (&g_Z[0][0])[gi] = 0.0f;
    }
    for (int i = tid; i < CC * 64; i += 256)
        xs[i >> 6][i & 63] = x[(((size_t)b * CC + (i >> 6)) * HH + h) * WW + wt * 64 + (i & 63)];
    __syncthreads();
    int p = tid & 63, grp = tid >> 6;
    int s = b * 4 + (h >> 6) * 2 + wt;
    int n = (h & 63) * 64 + p;
    const float* Wm = (grp == 0) ? Wq : (grp == 1) ? Wk : (grp == 2) ? Wa : Wb;
    const float* bv = (grp == 0) ? bq : (grp == 1) ? bk : (grp == 2) ? ba : bb;
    if (grp < 2) {
        float av[CC];
        #pragma unroll 1
        for (int oc = 0; oc < CC; oc++) {
            float acc = bv[oc];
            const float4* wr = (const float4*)(Wm + oc * CC);
            #pragma unroll
            for (int c4 = 0; c4 < 16; c4++) {
                float4 w = wr[c4];
                acc += w.x * xs[c4 * 4][p] + w.y * xs[c4 * 4 + 1][p] + w.z * xs[c4 * 4 + 2][p] + w.w * xs[c4 * 4 + 3][p];
            }
            av[oc] = acc;
        }
        uint32_t* ph = (uint32_t*)((grp == 0) ? &g_qh[s][n][0] : &g_kh[s][n][0]);
        uint32_t* pl = (uint32_t*)((grp == 0) ? &g_ql[s][n][0] : &g_kl[s][n][0]);
        #pragma unroll
        for (int c2 = 0; c2 < 32; c2++) {
            float v0 = av[2 * c2], v1 = av[2 * c2 + 1];
            float h0 = __bfloat162float(__float2bfloat16(v0));
            float h1 = __bfloat162float(__float2bfloat16(v1));
            ph[c2] = pk(v0, v1);
            pl[c2] = pk(v0 - h0, v1 - h1);
        }
    } else {
        float* outp = (grp == 2) ? &g_a[s][0][0] : &g_b[s][0][0];
        #pragma unroll 1
        for (int oc = 0; oc < CC; oc++) {
            float acc = bv[oc];
            const float4* wr = (const float4*)(Wm + oc * CC);
            #pragma unroll
            for (int c4 = 0; c4 < 16; c4++) {
                float4 w = wr[c4];
                acc += w.x * xs[c4 * 4][p] + w.y * xs[c4 * 4 + 1][p] + w.z * xs[c4 * 4 + 2][p] + w.w * xs[c4 * 4 + 3][p];
            }
            outp[oc * NN + n] = acc;
        }
    }
}

// -------- ez: E = exp(q^T k / 8) via mma.sync, bf16 store, Z rowsums --------
__global__ void __launch_bounds__(256, 2) ez_kernel() {
    extern __shared__ char sm[];
    uint32_t sb = s2u(sm);
    int s = blockIdx.z, n0 = blockIdx.y * 128, m0 = blockIdx.x * 128;
    int tid = threadIdx.x, w = tid >> 5, ln = tid & 31;
    const __nv_bfloat16* srcs[4] = {&g_qh[s][n0][0], &g_ql[s][n0][0], &g_kh[s][m0][0], &g_kl[s][m0][0]};
    #pragma unroll
    for (int pl = 0; pl < 4; pl++) {
        const uint4* sp = (const uint4*)srcs[pl];
        char* dp = sm + pl * 18432;
        for (int u = tid; u < 1024; u += 256)
            *(uint4*)(dp + (u >> 3) * 144 + (u & 7) * 16) = sp[u];
    }
    __syncthreads();
    int n_off = (w >> 1) * 32, m_off = (w & 1) * 64;
    int g = ln >> 2, tg = ln & 3;
    float acc[2][8][4];
    #pragma unroll
    for (int i = 0; i < 2; i++)
        #pragma unroll
        for (int j = 0; j < 8; j++)
            #pragma unroll
            for (int q = 0; q < 4; q++) acc[i][j][q] = 0.f;
    #pragma unroll 1
    for (int pass = 0; pass < 3; pass++) {
        uint32_t qb = sb + ((pass == 2) ? 18432u : 0u);
        uint32_t kb = sb + 36864u + ((pass == 1) ? 18432u : 0u);
        #pragma unroll
        for (int k16 = 0; k16 < 4; k16++) {
            int cb = k16 * 16;
            uint32_t aF[2][4];
            #pragma unroll
            for (int mf = 0; mf < 2; mf++)
                ldsm4(aF[mf], qb + (n_off + mf * 16 + (ln & 15)) * 144 + (cb + (ln >> 4) * 8) * 2);
            #pragma unroll
            for (int np = 0; np < 4; np++) {
                uint32_t bF[4];
                ldsm4(bF, kb + (m_off + np * 16 + (ln & 7) + ((ln >> 4) << 3)) * 144 + (cb + ((ln >> 3) & 1) * 8) * 2);
                mma16816(acc[0][2 * np], aF[0], bF);
                mma16816(acc[0][2 * np + 1], aF[0], bF + 2);
                mma16816(acc[1][2 * np], aF[1], bF);
                mma16816(acc[1][2 * np + 1], aF[1], bF + 2);
            }
        }
    }
    // exp + row sums
    #pragma unroll
    for (int mf = 0; mf < 2; mf++) {
        float r0 = 0.f, r1 = 0.f;
        #pragma unroll
        for (int nf = 0; nf < 8; nf++) {
            #pragma unroll
            for (int q = 0; q < 4; q++) acc[mf][nf][q] = fexp8(acc[mf][nf][q]);
            r0 += acc[mf][nf][0] + acc[mf][nf][1];
            r1 += acc[mf][nf][2] + acc[mf][nf][3];
        }
        r0 += __shfl_xor_sync(~0u, r0, 1); r0 += __shfl_xor_sync(~0u, r0, 2);
        r1 += __shfl_xor_sync(~0u, r1, 1); r1 += __shfl_xor_sync(~0u, r1, 2);
        if (tg == 0) {
            atomicAdd(&g_Z[s][n0 + n_off + mf * 16 + g], r0);
            atomicAdd(&g_Z[s][n0 + n_off + mf * 16 + g + 8], r1);
        }
    }
    __syncthreads();
    // stage hi plane [128][136] bf16 (272B rows) for coalesced store
    #pragma unroll
    for (int mf = 0; mf < 2; mf++)
        #pragma unroll
        for (int nf = 0; nf < 8; nf++) {
            int col = m_off + nf * 8 + 2 * tg;
            int r0w = n_off + mf * 16 + g, r1w = r0w + 8;
            *(uint32_t*)(sm + r0w * 272 + col * 2) = pk(acc[mf][nf][0], acc[mf][nf][1]);
            *(uint32_t*)(sm + r1w * 272 + col * 2) = pk(acc[mf][nf][2], acc[mf][nf][3]);
        }
    __syncthreads();
    for (int u = tid; u < 2048; u += 256) {
        int row = u >> 4, ch = u & 15;
        *(uint4*)&g_Eh[((size_t)s * NN + n0 + row) * NN + m0 + ch * 8] = *(uint4*)(sm + row * 272 + ch * 16);
    }
}

// -------- scale a by 1/Z, split a,b into stacked hi/lo bf16 --------
__global__ void scale_split_kernel() {
    int n = blockIdx.x * 256 + threadIdx.x, c = blockIdx.y, s = blockIdx.z;
    float rz = 1.0f / g_Z[s][n];
    if (c == 0) g_rZ[s][n] = rz;
    float av = g_a[s][c][n] * rz, bv = g_b[s][c][n];
    float ah = __bfloat162float(__float2bfloat16(av));
    float bh = __bfloat162float(__float2bfloat16(bv));
    g_as[s][c][n] = __float2bfloat16(av);
    g_as[s][c + CC][n] = __float2bfloat16(av - ah);
    g_bs[s][c][n] = __float2bfloat16(bv);
    g_bs[s][c + CC][n] = __float2bfloat16(bv - bh);
}

// -------- outk: out = a'@E + diag(rZ)*(b @ E-rows) via mma.sync --------
__global__ void __launch_bounds__(256, 2) outk_kernel() {
    extern __shared__ char sm[];
    uint32_t sb = s2u(sm);
    int s = blockIdx.y, m0 = blockIdx.x * 128;
    int tid = threadIdx.x, w = tid >> 5, ln = tid & 31;
    const uint32_t AH = 0, AL = 9216, BH = 18432, BL = 27648;
    const uint32_t E1H = 36864, E2H = 54272;
    int c_off = (w >> 1) * 16, mw = (w & 1) * 64;
    int g = ln >> 2, tg = ln & 3;
    float ac1[8][4], ac2[8][4];
    #pragma unroll
    for (int i = 0; i < 8; i++)
        #pragma unroll
        for (int q = 0; q < 4; q++) { ac1[i][q] = 0.f; ac2[i][q] = 0.f; }

    #pragma unroll 1
    for (int it = 0; it < 64; it++) {
        int j0 = it * 64;
        __syncthreads();
        for (int u = tid; u < 2048; u += 256) {
            int pl = u >> 9, rem = u & 511, row = rem >> 3, ch = rem & 7;
            const __nv_bfloat16* src = (pl < 2) ? &g_as[s][row + (pl & 1) * 64][j0]
                                                : &g_bs[s][row + (pl & 1) * 64][j0];
            *(uint4*)(sm + pl * 9216 + row * 144 + ch * 16) = ((const uint4*)src)[ch];
        }
        for (int u = tid; u < 1024; u += 256) {
            int row = u >> 4, ch = u & 15;
            *(uint4*)(sm + E1H + row * 272 + ch * 16) =
                ((const uint4*)&g_Eh[((size_t)s * NN + j0 + row) * NN + m0])[ch];
        }
        for (int u = tid; u < 1024; u += 256) {
            int row = u >> 3, ch = u & 7;
            *(uint4*)(sm + E2H + row * 144 + ch * 16) =
                ((const uint4*)&g_Eh[((size_t)s * NN + m0 + row) * NN + j0])[ch];
        }
        __syncthreads();
        #pragma unroll
        for (int kb = 0; kb < 4; kb++) {
            int jb = kb * 16;
            uint32_t ah[4], al[4], bh[4], bl[4];
            uint32_t arow = (c_off + (ln & 15)) * 144 + (jb + (ln >> 4) * 8) * 2;
            ldsm4(ah, sb + AH + arow);
            ldsm4(al, sb + AL + arow);
            ldsm4(bh, sb + BH + arow);
            ldsm4(bl, sb + BL + arow);
            #pragma unroll
            for (int np = 0; np < 4; np++) {
                int mb = mw + np * 16;
                uint32_t e1h[4], e2h[4];
                ldsm4t(e1h, sb + E1H + (jb + (ln & 15)) * 272 + (mb + (ln >> 4) * 8) * 2);
                ldsm4(e2h, sb + E2H + (mb + (ln & 7) + ((ln >> 4) << 3)) * 144 + (jb + ((ln >> 3) & 1) * 8) * 2);
                mma16816(ac1[2 * np], ah, e1h);     mma16816(ac1[2 * np + 1], ah, e1h + 2);
                mma16816(ac1[2 * np], al, e1h);     mma16816(ac1[2 * np + 1], al, e1h + 2);
                mma16816(ac2[2 * np], bh, e2h);     mma16816(ac2[2 * np + 1], bh, e2h + 2);
                mma16816(ac2[2 * np], bl, e2h);     mma16816(ac2[2 * np + 1], bl, e2h + 2);
            }
        }
    }
    #pragma unroll
    for (int nf = 0; nf < 8; nf++) {
        int m = m0 + mw + nf * 8 + 2 * tg;
        float rz0 = g_rZ[s][m], rz1 = g_rZ[s][m + 1];
        int c0 = c_off + g;
        g_o[s][c0][m]     = ac1[nf][0] + rz0 * ac2[nf][0];
        g_o[s][c0][m + 1] = ac1[nf][1] + rz1 * ac2[nf][1];
        g_o[s][c0 + 8][m]     = ac1[nf][2] + rz0 * ac2[nf][2];
        g_o[s][c0 + 8][m + 1] = ac1[nf][3] + rz1 * ac2[nf][3];
    }
}

// -------- final 1x1 conv + un-regionize --------
__global__ void finalconv_kernel(const float* __restrict__ Wo, const float* __restrict__ bo,
                                 float* __restrict__ out) {
    __shared__ float os[CC][64];
    int wt = blockIdx.x, h = blockIdx.y, b = blockIdx.z, tid = threadIdx.x;
    int s = b * 4 + (h >> 6) * 2 + wt;
    int nb = (h & 63) * 64;
    for (int i = tid; i < CC * 64; i += 256)
        os[i >> 6][i & 63] = g_o[s][i >> 6][nb + (i & 63)];
    __syncthreads();
    int p = tid & 63, grp = tid >> 6;
    #pragma unroll 1
    for (int i = 0; i < 16; i++) {
        int oc = grp * 16 + i;
        float acc = bo[oc];
        const float4* wr = (const float4*)(Wo + oc * CC);
        #pragma unroll
        for (int c4 = 0; c4 < 16; c4++) {
            float4 w = wr[c4];
            acc += w.x * os[c4 * 4][p] + w.y * os[c4 * 4 + 1][p] + w.z * os[c4 * 4 + 2][p] + w.w * os[c4 * 4 + 3][p];
        }
        out[(((size_t)b * CC + oc) * HH + h) * WW + wt * 64 + p] = acc;
    }
}

extern "C" void kernel_launch(void* const* d_in, const int* in_sizes, int n_in,
                              void* d_out, int out_size) {
    const float* x = (const float*)d_in[0];
    const float *Wq = (const float*)d_in[1], *bq = (const float*)d_in[2];
    const float *Wk = (const float*)d_in[3], *bk = (const float*)d_in[4];
    const float *Wa = (const float*)d_in[5], *ba = (const float*)d_in[6];
    const float *Wb = (const float*)d_in[7], *bb = (const float*)d_in[8];
    const float *Wo = (const float*)d_in[9], *bo = (const float*)d_in[10];
    float* out = (float*)d_out;

    const int EZ_SM = 73728;
    const int OK_SM = 72704;
    cudaFuncSetAttribute(ez_kernel, cudaFuncAttributeMaxDynamicSharedMemorySize, EZ_SM);
    cudaFuncSetAttribute(outk_kernel, cudaFuncAttributeMaxDynamicSharedMemorySize, OK_SM);

    conv4_kernel<<<dim3(2, HH, BB), 256>>>(x, Wq, bq, Wk, bk, Wa, ba, Wb, bb);
    ez_kernel<<<dim3(32, 32, NS), 256, EZ_SM>>>();
    scale_split_kernel<<<dim3(NN / 256, CC, NS), 256>>>();
    outk_kernel<<<dim3(32, NS), 256, OK_SM>>>();
    finalconv_kernel<<<dim3(2, HH, BB), 256>>>(Wo, bo, out);
}

// round 17
// speedup vs baseline: 1.0833x; 1.0734x over previous
#include <cuda_runtime.h>
#include <cuda_bf16.h>
#include <cstdint>

#define CC 64
#define HH 128
#define WW 128
#define NN 4096
#define NS 8
#define BB 2

__device__ float g_a[NS][CC][NN];
__device__ float g_b[NS][CC][NN];
__device__ float g_Z[NS][NN];
__device__ float g_rZ[NS][NN];
__device__ float g_o[NS][CC][NN];
__device__ float g_o2[NS][CC][NN];
__device__ __nv_bfloat16 g_qh[NS][NN][CC], g_ql[NS][NN][CC];
__device__ __nv_bfloat16 g_kh[NS][NN][CC], g_kl[NS][NN][CC];
__device__ __nv_bfloat16 g_as[NS][2 * CC][NN], g_bs[NS][2 * CC][NN];
__device__ __nv_bfloat16 g_Eh[(size_t)NS * NN * NN];

__device__ __forceinline__ uint32_t s2u(const void* p) {
    uint32_t a;
    asm("{ .reg .u64 t; cvta.to.shared.u64 t, %1; cvt.u32.u64 %0, t; }" : "=r"(a) : "l"(p));
    return a;
}
__device__ __forceinline__ void ldsm4(uint32_t* r, uint32_t a) {
    asm volatile("ldmatrix.sync.aligned.m8n8.x4.shared.b16 {%0,%1,%2,%3}, [%4];"
        : "=r"(r[0]), "=r"(r[1]), "=r"(r[2]), "=r"(r[3]) : "r"(a));
}
__device__ __forceinline__ void ldsm4t(uint32_t* r, uint32_t a) {
    asm volatile("ldmatrix.sync.aligned.m8n8.x4.trans.shared.b16 {%0,%1,%2,%3}, [%4];"
        : "=r"(r[0]), "=r"(r[1]), "=r"(r[2]), "=r"(r[3]) : "r"(a));
}
__device__ __forceinline__ void mma16816(float* d, const uint32_t* a, const uint32_t* b) {
    asm volatile("mma.sync.aligned.m16n8k16.row.col.f32.bf16.bf16.f32 "
        "{%0,%1,%2,%3}, {%4,%5,%6,%7}, {%8,%9}, {%0,%1,%2,%3};"
        : "+f"(d[0]), "+f"(d[1]), "+f"(d[2]), "+f"(d[3])
        : "r"(a[0]), "r"(a[1]), "r"(a[2]), "r"(a[3]), "r"(b[0]), "r"(b[1]));
}
__device__ __forceinline__ uint32_t pk(float a, float b) {
    __nv_bfloat162 t(__float2bfloat16(a), __float2bfloat16(b));
    return *reinterpret_cast<uint32_t*>(&t);
}

// exp(s/8) on the FMA pipe
__device__ __forceinline__ float fexp8(float s) {
    const float MAGIC = 12582912.0f;  // 1.5 * 2^23
    float y = s * 0.18033688011112042f;
    float t = y + MAGIC;
    float f = y - (t - MAGIC);
    float p = 1.60218936e-3f;
    p = fmaf(p, f, 9.61739095e-3f);
    p = fmaf(p, f, 5.55041086e-2f);
    p = fmaf(p, f, 2.40226507e-1f);
    p = fmaf(p, f, 6.93147182e-1f);
    p = fmaf(p, f, 1.0f);
    return __int_as_float(__float_as_int(p) + (__float_as_int(t) << 23));
}

// -------- conv (+ inline Z zeroing): q,k -> split bf16 [n][c]; a,b -> fp32 [c][n] --------
__global__ void conv4_kernel(const float* __restrict__ x,
                             const float* __restrict__ Wq, const float* __restrict__ bq,
                             const float* __restrict__ Wk, const float* __restrict__ bk,
                             const float* __restrict__ Wa, const float* __restrict__ ba,
                             const float* __restrict__ Wb, const float* __restrict__ bb) {
    __shared__ float xs[CC][64];
    int wt = blockIdx.x, h = blockIdx.y, b = blockIdx.z, tid = threadIdx.x;
    {
        int gi = (((b * HH) + h) * 2 + wt) * 256 + tid;
        if (gi < NS * NN) (&g_Z[0][0])[gi] = 0.0f;
    }
    for (int i = tid; i < CC * 64; i += 256)
        xs[i >> 6][i & 63] = x[(((size_t)b * CC + (i >> 6)) * HH + h) * WW + wt * 64 + (i & 63)];
    __syncthreads();
    int p = tid & 63, grp = tid >> 6;
    int s = b * 4 + (h >> 6) * 2 + wt;
    int n = (h & 63) * 64 + p;
    const float* Wm = (grp == 0) ? Wq : (grp == 1) ? Wk : (grp == 2) ? Wa : Wb;
    const float* bv = (grp == 0) ? bq : (grp == 1) ? bk : (grp == 2) ? ba : bb;
    if (grp < 2) {
        float av[CC];
        #pragma unroll 1
        for (int oc = 0; oc < CC; oc++) {
            float acc = bv[oc];
            const float4* wr = (const float4*)(Wm + oc * CC);
            #pragma unroll
            for (int c4 = 0; c4 < 16; c4++) {
                float4 w = wr[c4];
                acc += w.x * xs[c4 * 4][p] + w.y * xs[c4 * 4 + 1][p] + w.z * xs[c4 * 4 + 2][p] + w.w * xs[c4 * 4 + 3][p];
            }
            av[oc] = acc;
        }
        uint32_t* ph = (uint32_t*)((grp == 0) ? &g_qh[s][n][0] : &g_kh[s][n][0]);
        uint32_t* pl = (uint32_t*)((grp == 0) ? &g_ql[s][n][0] : &g_kl[s][n][0]);
        #pragma unroll
        for (int c2 = 0; c2 < 32; c2++) {
            float v0 = av[2 * c2], v1 = av[2 * c2 + 1];
            float h0 = __bfloat162float(__float2bfloat16(v0));
            float h1 = __bfloat162float(__float2bfloat16(v1));
            ph[c2] = pk(v0, v1);
            pl[c2] = pk(v0 - h0, v1 - h1);
        }
    } else {
        float* outp = (grp == 2) ? &g_a[s][0][0] : &g_b[s][0][0];
        #pragma unroll 1
        for (int oc = 0; oc < CC; oc++) {
            float acc = bv[oc];
            const float4* wr = (const float4*)(Wm + oc * CC);
            #pragma unroll
            for (int c4 = 0; c4 < 16; c4++) {
                float4 w = wr[c4];
                acc += w.x * xs[c4 * 4][p] + w.y * xs[c4 * 4 + 1][p] + w.z * xs[c4 * 4 + 2][p] + w.w * xs[c4 * 4 + 3][p];
            }
            outp[oc * NN + n] = acc;
        }
    }
}

// -------- ez: E = exp(q^T k / 8) via mma.sync, bf16 store, Z rowsums --------
__global__ void __launch_bounds__(256, 2) ez_kernel() {
    extern __shared__ char sm[];
    uint32_t sb = s2u(sm);
    int s = blockIdx.z, n0 = blockIdx.y * 128, m0 = blockIdx.x * 128;
    int tid = threadIdx.x, w = tid >> 5, ln = tid & 31;
    const __nv_bfloat16* srcs[4] = {&g_qh[s][n0][0], &g_ql[s][n0][0], &g_kh[s][m0][0], &g_kl[s][m0][0]};
    #pragma unroll
    for (int pl = 0; pl < 4; pl++) {
        const uint4* sp = (const uint4*)srcs[pl];
        char* dp = sm + pl * 18432;
        for (int u = tid; u < 1024; u += 256)
            *(uint4*)(dp + (u >> 3) * 144 + (u & 7) * 16) = sp[u];
    }
    __syncthreads();
    int n_off = (w >> 1) * 32, m_off = (w & 1) * 64;
    int g = ln >> 2, tg = ln & 3;
    float acc[2][8][4];
    #pragma unroll
    for (int i = 0; i < 2; i++)
        #pragma unroll
        for (int j = 0; j < 8; j++)
            #pragma unroll
            for (int q = 0; q < 4; q++) acc[i][j][q] = 0.f;
    #pragma unroll 1
    for (int pass = 0; pass < 3; pass++) {
        uint32_t qb = sb + ((pass == 2) ? 18432u : 0u);
        uint32_t kb = sb + 36864u + ((pass == 1) ? 18432u : 0u);
        #pragma unroll
        for (int k16 = 0; k16 < 4; k16++) {
            int cb = k16 * 16;
            uint32_t aF[2][4];
            #pragma unroll
            for (int mf = 0; mf < 2; mf++)
                ldsm4(aF[mf], qb + (n_off + mf * 16 + (ln & 15)) * 144 + (cb + (ln >> 4) * 8) * 2);
            #pragma unroll
            for (int np = 0; np < 4; np++) {
                uint32_t bF[4];
                ldsm4(bF, kb + (m_off + np * 16 + (ln & 7) + ((ln >> 4) << 3)) * 144 + (cb + ((ln >> 3) & 1) * 8) * 2);
                mma16816(acc[0][2 * np], aF[0], bF);
                mma16816(acc[0][2 * np + 1], aF[0], bF + 2);
                mma16816(acc[1][2 * np], aF[1], bF);
                mma16816(acc[1][2 * np + 1], aF[1], bF + 2);
            }
        }
    }
    #pragma unroll
    for (int mf = 0; mf < 2; mf++) {
        float r0 = 0.f, r1 = 0.f;
        #pragma unroll
        for (int nf = 0; nf < 8; nf++) {
            #pragma unroll
            for (int q = 0; q < 4; q++) acc[mf][nf][q] = fexp8(acc[mf][nf][q]);
            r0 += acc[mf][nf][0] + acc[mf][nf][1];
            r1 += acc[mf][nf][2] + acc[mf][nf][3];
        }
        r0 += __shfl_xor_sync(~0u, r0, 1); r0 += __shfl_xor_sync(~0u, r0, 2);
        r1 += __shfl_xor_sync(~0u, r1, 1); r1 += __shfl_xor_sync(~0u, r1, 2);
        if (tg == 0) {
            atomicAdd(&g_Z[s][n0 + n_off + mf * 16 + g], r0);
            atomicAdd(&g_Z[s][n0 + n_off + mf * 16 + g + 8], r1);
        }
    }
    __syncthreads();
    #pragma unroll
    for (int mf = 0; mf < 2; mf++)
        #pragma unroll
        for (int nf = 0; nf < 8; nf++) {
            int col = m_off + nf * 8 + 2 * tg;
            int r0w = n_off + mf * 16 + g, r1w = r0w + 8;
            *(uint32_t*)(sm + r0w * 272 + col * 2) = pk(acc[mf][nf][0], acc[mf][nf][1]);
            *(uint32_t*)(sm + r1w * 272 + col * 2) = pk(acc[mf][nf][2], acc[mf][nf][3]);
        }
    __syncthreads();
    for (int u = tid; u < 2048; u += 256) {
        int row = u >> 4, ch = u & 15;
        *(uint4*)&g_Eh[((size_t)s * NN + n0 + row) * NN + m0 + ch * 8] = *(uint4*)(sm + row * 272 + ch * 16);
    }
}

// -------- scale a by 1/Z, split a,b into stacked hi/lo bf16 --------
__global__ void scale_split_kernel() {
    int n = blockIdx.x * 256 + threadIdx.x, c = blockIdx.y, s = blockIdx.z;
    float rz = 1.0f / g_Z[s][n];
    if (c == 0) g_rZ[s][n] = rz;
    float av = g_a[s][c][n] * rz, bv = g_b[s][c][n];
    float ah = __bfloat162float(__float2bfloat16(av));
    float bh = __bfloat162float(__float2bfloat16(bv));
    g_as[s][c][n] = __float2bfloat16(av);
    g_as[s][c + CC][n] = __float2bfloat16(av - ah);
    g_bs[s][c][n] = __float2bfloat16(bv);
    g_bs[s][c + CC][n] = __float2bfloat16(bv - bh);
}

// -------- outk: 64m tiles, j-split x2, 3 blocks/SM target --------
__global__ void __launch_bounds__(256, 3) outk_kernel() {
    extern __shared__ char sm[];
    uint32_t sb = s2u(sm);
    int s = blockIdx.z, m0 = blockIdx.x * 64, jh = blockIdx.y;
    int tid = threadIdx.x, w = tid >> 5, ln = tid & 31;
    const uint32_t AH = 0, AL = 9216, BH = 18432, BL = 27648;
    const uint32_t E1H = 36864, E2H = 46080;   // each 64 rows x 144B = 9216
    int c_off = (w >> 1) * 16, mw = (w & 1) * 32;
    int g = ln >> 2, tg = ln & 3;
    float ac1[4][4], ac2[4][4];
    #pragma unroll
    for (int i = 0; i < 4; i++)
        #pragma unroll
        for (int q = 0; q < 4; q++) { ac1[i][q] = 0.f; ac2[i][q] = 0.f; }

    #pragma unroll 1
    for (int it = 0; it < 32; it++) {
        int j0 = jh * 2048 + it * 64;
        __syncthreads();
        // A planes [64c stacked hi/lo][64j], 144B rows
        for (int u = tid; u < 2048; u += 256) {
            int pl = u >> 9, rem = u & 511, row = rem >> 3, ch = rem & 7;
            const __nv_bfloat16* src = (pl < 2) ? &g_as[s][row + (pl & 1) * 64][j0]
                                                : &g_bs[s][row + (pl & 1) * 64][j0];
            *(uint4*)(sm + pl * 9216 + row * 144 + ch * 16) = ((const uint4*)src)[ch];
        }
        // E1 [64j][64m] (term1 via ldmatrix.trans)
        for (int u = tid; u < 512; u += 256) {
            int row = u >> 3, ch = u & 7;
            *(uint4*)(sm + E1H + row * 144 + ch * 16) =
                ((const uint4*)&g_Eh[((size_t)s * NN + j0 + row) * NN + m0])[ch];
        }
        // E2 [64m][64j] (term2 K-major direct)
        for (int u = tid; u < 512; u += 256) {
            int row = u >> 3, ch = u & 7;
            *(uint4*)(sm + E2H + row * 144 + ch * 16) =
                ((const uint4*)&g_Eh[((size_t)s * NN + m0 + row) * NN + j0])[ch];
        }
        __syncthreads();
        #pragma unroll
        for (int kb = 0; kb < 4; kb++) {
            int jb = kb * 16;
            uint32_t ah[4], al[4], bh[4], bl[4];
            uint32_t arow = (c_off + (ln & 15)) * 144 + (jb + (ln >> 4) * 8) * 2;
            ldsm4(ah, sb + AH + arow);
            ldsm4(al, sb + AL + arow);
            ldsm4(bh, sb + BH + arow);
            ldsm4(bl, sb + BL + arow);
            #pragma unroll
            for (int np = 0; np < 2; np++) {
                int mb = mw + np * 16;
                uint32_t e1h[4], e2h[4];
                ldsm4t(e1h, sb + E1H + (jb + (ln & 15)) * 144 + (mb + (ln >> 4) * 8) * 2);
                ldsm4(e2h, sb + E2H + (mb + (ln & 7) + ((ln >> 4) << 3)) * 144 + (jb + ((ln >> 3) & 1) * 8) * 2);
                mma16816(ac1[2 * np], ah, e1h);     mma16816(ac1[2 * np + 1], ah, e1h + 2);
                mma16816(ac1[2 * np], al, e1h);     mma16816(ac1[2 * np + 1], al, e1h + 2);
                mma16816(ac2[2 * np], bh, e2h);     mma16816(ac2[2 * np + 1], bh, e2h + 2);
                mma16816(ac2[2 * np], bl, e2h);     mma16816(ac2[2 * np + 1], bl, e2h + 2);
            }
        }
    }
    float* outp = jh ? &g_o2[0][0][0] : &g_o[0][0][0];
    #pragma unroll
    for (int nf = 0; nf < 4; nf++) {
        int m = m0 + mw + nf * 8 + 2 * tg;
        float rz0 = g_rZ[s][m], rz1 = g_rZ[s][m + 1];
        int c0 = c_off + g;
        size_t base = ((size_t)s * CC + c0) * NN;
        outp[base + m]     = ac1[nf][0] + rz0 * ac2[nf][0];
        outp[base + m + 1] = ac1[nf][1] + rz1 * ac2[nf][1];
        outp[base + 8 * NN + m]     = ac1[nf][2] + rz0 * ac2[nf][2];
        outp[base + 8 * NN + m + 1] = ac1[nf][3] + rz1 * ac2[nf][3];
    }
}

// -------- final 1x1 conv + un-regionize (sums the two j-half partials) --------
__global__ void finalconv_kernel(const float* __restrict__ Wo, const float* __restrict__ bo,
                                 float* __restrict__ out) {
    __shared__ float os[CC][64];
    int wt = blockIdx.x, h = blockIdx.y, b = blockIdx.z, tid = threadIdx.x;
    int s = b * 4 + (h >> 6) * 2 + wt;
    int nb = (h & 63) * 64;
    for (int i = tid; i < CC * 64; i += 256)
        os[i >> 6][i & 63] = g_o[s][i >> 6][nb + (i & 63)] + g_o2[s][i >> 6][nb + (i & 63)];
    __syncthreads();
    int p = tid & 63, grp = tid >> 6;
    #pragma unroll 1
    for (int i = 0; i < 16; i++) {
        int oc = grp * 16 + i;
        float acc = bo[oc];
        const float4* wr = (const float4*)(Wo + oc * CC);
        #pragma unroll
        for (int c4 = 0; c4 < 16; c4++) {
            float4 w = wr[c4];
            acc += w.x * os[c4 * 4][p] + w.y * os[c4 * 4 + 1][p] + w.z * os[c4 * 4 + 2][p] + w.w * os[c4 * 4 + 3][p];
        }
        out[(((size_t)b * CC + oc) * HH + h) * WW + wt * 64 + p] = acc;
    }
}

extern "C" void kernel_launch(void* const* d_in, const int* in_sizes, int n_in,
                              void* d_out, int out_size) {
    const float* x = (const float*)d_in[0];
    const float *Wq = (const float*)d_in[1], *bq = (const float*)d_in[2];
    const float *Wk = (const float*)d_in[3], *bk = (const float*)d_in[4];
    const float *Wa = (const float*)d_in[5], *ba = (const float*)d_in[6];
    const float *Wb = (const float*)d_in[7], *bb = (const float*)d_in[8];
    const float *Wo = (const float*)d_in[9], *bo = (const float*)d_in[10];
    float* out = (float*)d_out;

    const int EZ_SM = 73728;
    const int OK_SM = 55296;
    cudaFuncSetAttribute(ez_kernel, cudaFuncAttributeMaxDynamicSharedMemorySize, EZ_SM);
    cudaFuncSetAttribute(outk_kernel, cudaFuncAttributeMaxDynamicSharedMemorySize, OK_SM);

    conv4_kernel<<<dim3(2, HH, BB), 256>>>(x, Wq, bq, Wk, bk, Wa, ba, Wb, bb);
    ez_kernel<<<dim3(32, 32, NS), 256, EZ_SM>>>();
    scale_split_kernel<<<dim3(NN / 256, CC, NS), 256>>>();
    outk_kernel<<<dim3(64, 2, NS), 256, OK_SM>>>();
    finalconv_kernel<<<dim3(2, HH, BB), 256>>>(Wo, bo, out);
}